// round 12
// baseline (speedup 1.0000x reference)
#include <cuda_runtime.h>
#include <cuda_bf16.h>
#include <math.h>

// Problem constants (fixed by setup_inputs)
#define N_ROWS   128
#define IN_F     1024
#define OUT_F    512
#define NB       32          // IN_F / BLOCK_SIZE
#define BS       32          // BLOCK_SIZE
#define NDELAY   14          // CYCLE_BUDGET - ONLINE_DELAY
#define WARPS_PER_CTA 8

// Scratch (device globals; no allocation allowed)
__device__ float g_xq[N_ROWS * IN_F];
__device__ float g_wq[OUT_F * IN_F];
__device__ float g_l2xs[N_ROWS * NB];
__device__ float g_l2ws[OUT_F * NB];
__device__ float g_xs[N_ROWS * NB];
__device__ float g_ws[OUT_F * NB];
__device__ int   g_xemax[N_ROWS * NB];

// ---------------------------------------------------------------------------
// Quantization: one warp per 32-element block.
//   scale = max(max|v|, 1e-30); xn = v/scale;
//   e = floor(log2|xn|); step = 2^(e-3); q = rint(xn/step)*step
// Also emits log2(scale), scale, and (x only) per-block max of
// floor(log2|q|) (zeros count as -60) for intra-block delays.
// ---------------------------------------------------------------------------
__device__ __forceinline__ void quant_block(const float* __restrict__ in,
                                            float* __restrict__ q,
                                            float* __restrict__ l2s,
                                            float* __restrict__ sc,
                                            int*   __restrict__ emaxb, // may be null
                                            int warp, int lane)
{
    const int idx = warp * BS + lane;
    float v = in[idx];
    float a = fabsf(v);

    float m = a;
    #pragma unroll
    for (int off = 16; off; off >>= 1)
        m = fmaxf(m, __shfl_xor_sync(0xffffffffu, m, off));

    float scale = fmaxf(m, 1e-30f);
    float xn = v / scale;
    float aq = fabsf(xn);
    float qv = 0.0f;
    if (aq > 0.0f) {
        float e = floorf(log2f(fmaxf(aq, 1e-45f)));
        float step = ldexpf(1.0f, (int)e - 3);
        if (step > 0.0f) qv = rintf(xn / step) * step;
    }
    q[idx] = qv;

    float el = (qv != 0.0f) ? floorf(log2f(fabsf(qv))) : -60.0f;
    #pragma unroll
    for (int off = 16; off; off >>= 1)
        el = fmaxf(el, __shfl_xor_sync(0xffffffffu, el, off));

    if (lane == 0) {
        l2s[warp] = log2f(scale);
        sc[warp]  = scale;
        if (emaxb) emaxb[warp] = (int)el;
    }
}

__global__ void quant_x_kernel(const float* __restrict__ in)
{
    int warp = (blockIdx.x * blockDim.x + threadIdx.x) >> 5;
    int lane = threadIdx.x & 31;
    if (warp >= N_ROWS * NB) return;
    quant_block(in, g_xq, g_l2xs, g_xs, g_xemax, warp, lane);
}

__global__ void quant_w_kernel(const float* __restrict__ in)
{
    int warp = (blockIdx.x * blockDim.x + threadIdx.x) >> 5;
    int lane = threadIdx.x & 31;
    if (warp >= OUT_F * NB) return;
    quant_block(in, g_wq, g_l2ws, g_ws, (int*)nullptr, warp, lane);
}

// ---------------------------------------------------------------------------
// Main kernel: one warp per (n, o) output. 8 warps/CTA share the same n,
// so the x row + x-side block metadata is staged in shared memory.
// Lane k handles element k of each 32-element block; serial loop over blocks.
// ---------------------------------------------------------------------------
__global__ void __launch_bounds__(256, 8)
msd_gemm_kernel(const float* __restrict__ bias, float* __restrict__ out)
{
    const int warp = threadIdx.x >> 5;
    const int lane = threadIdx.x & 31;
    const int wglob = blockIdx.x * WARPS_PER_CTA + warp;
    const int n = wglob >> 9;        // /OUT_F
    const int o = wglob & (OUT_F - 1);

    __shared__ float s_x[IN_F];
    __shared__ float s_l2xs[NB];
    __shared__ float s_xs[NB];
    __shared__ int   s_xemax[NB];

    // cooperative load of the shared x row (all warps: same n within CTA)
    for (int i = threadIdx.x; i < IN_F; i += 256)
        s_x[i] = g_xq[n * IN_F + i];
    if (threadIdx.x < NB) {
        s_l2xs[threadIdx.x]  = g_l2xs[n * NB + threadIdx.x];
        s_xs[threadIdx.x]    = g_xs[n * NB + threadIdx.x];
        s_xemax[threadIdx.x] = g_xemax[n * NB + threadIdx.x];
    }
    __syncthreads();

    // per-block (lane = block index) setup
    float l2 = s_l2xs[lane] + __ldg(&g_l2ws[o * NB + lane]);
    int ce = (int)floorf(l2);
    int emax = ce;
    #pragma unroll
    for (int off = 16; off; off >>= 1)
        emax = max(emax, __shfl_xor_sync(0xffffffffu, emax, off));

    float sb = s_xs[lane] * __ldg(&g_ws[o * NB + lane]);
    int   Cb = NDELAY - (emax - ce) - s_xemax[lane];

    const float* wrow = g_wq + o * IN_F;

    float acc = 0.0f;
    #pragma unroll 8
    for (int b = 0; b < NB; b++) {
        float sbb = __shfl_sync(0xffffffffu, sb, b);
        int   C   = __shfl_sync(0xffffffffu, Cb, b);
        float xv = s_x[b * BS + lane];
        float wv = __ldg(&wrow[b * BS + lane]);
        float p = xv * wv;
        int pb = __float_as_int(p);
        if ((pb & 0x7fffffff) == 0) continue;               // p == 0
        int ex = ((__float_as_int(xv) >> 23) & 255) - 127;  // floor(log2|x_q|)
        int nd = C + ex;                                    // NAF digit budget
        if (nd <= 0) continue;
        int ep = ((pb >> 23) & 255) - 127;                  // floor(log2|p|)

        float recon;
        if (ep >= -100) {
            // fast path: x_scaled = mantissa|implicit (exact), scale = 2^(23-ep)
            unsigned xs = (unsigned)(pb & 0x7FFFFF) | 0x800000u;
            unsigned xh = xs >> 1;
            unsigned s  = xs + xh;
            unsigned npos = s & ~xh;
            unsigned nneg = xh & ~s;
            int width = 32 - __clz(npos | nneg);
            int drop = max(width - nd, 0);
            unsigned keep = 0xFFFFFFFFu << drop;
            int val = (int)(npos & keep) - (int)(nneg & keep);
            recon = (float)val * __int_as_float((ep + 104) << 23); // *2^(ep-23)
        } else {
            // rare path: match JAX clip(23 - msb, -126, 126) semantics exactly
            int shift = min(23 - ep, 126);
            unsigned xs = (unsigned)rintf(ldexpf(fabsf(p), shift));
            unsigned xh = xs >> 1;
            unsigned s  = xs + xh;
            unsigned npos = s & ~xh;
            unsigned nneg = xh & ~s;
            unsigned comb = npos | nneg;
            int width = comb ? (32 - __clz(comb)) : 0;
            int drop = min(max(width - nd, 0), 31);
            unsigned keep = 0xFFFFFFFFu << drop;
            int val = (int)(npos & keep) - (int)(nneg & keep);
            recon = ldexpf((float)val, -shift);
        }
        acc = fmaf(sbb, copysignf(recon, p), acc);
    }

    #pragma unroll
    for (int off = 16; off; off >>= 1)
        acc += __shfl_xor_sync(0xffffffffu, acc, off);

    if (lane == 0)
        out[n * OUT_F + o] = acc + __ldg(&bias[o]);
}

extern "C" void kernel_launch(void* const* d_in, const int* in_sizes, int n_in,
                              void* d_out, int out_size)
{
    const float* x = (const float*)d_in[0];
    const float* w = (const float*)d_in[1];
    const float* bias = (const float*)d_in[2];
    float* out = (float*)d_out;
    (void)in_sizes; (void)n_in; (void)out_size;

    // Quantize x: 4096 blocks of 32; w: 16384 blocks of 32
    quant_x_kernel<<<(N_ROWS * NB * 32 + 255) / 256, 256>>>(x);
    quant_w_kernel<<<(OUT_F * NB * 32 + 255) / 256, 256>>>(w);

    // Main: one warp per (n,o); 65536 warps, 8 warps/CTA -> 8192 CTAs
    msd_gemm_kernel<<<(N_ROWS * OUT_F) / WARPS_PER_CTA, 256>>>(bias, out);
}

// round 16
// speedup vs baseline: 1.3035x; 1.3035x over previous
#include <cuda_runtime.h>
#include <cuda_bf16.h>
#include <math.h>

// Problem constants (fixed by setup_inputs)
#define N_ROWS   128
#define IN_F     1024
#define OUT_F    512
#define NB       32          // IN_F / BLOCK_SIZE
#define BS       32          // BLOCK_SIZE
#define NDELAY   14          // CYCLE_BUDGET - ONLINE_DELAY
#define WARPS_PER_CTA 8

// Scratch (device globals; no allocation allowed)
__device__ float g_xq[N_ROWS * IN_F];
__device__ float g_wq[OUT_F * IN_F];
__device__ float g_l2xs[N_ROWS * NB];
__device__ float g_l2ws[OUT_F * NB];
__device__ float g_xs[N_ROWS * NB];
__device__ float g_ws[OUT_F * NB];
__device__ int   g_xemax[N_ROWS * NB];

// ---------------------------------------------------------------------------
// Quantization: one warp per 32-element block (x and w merged in one launch).
// ---------------------------------------------------------------------------
__device__ __forceinline__ void quant_block(const float* __restrict__ in,
                                            float* __restrict__ q,
                                            float* __restrict__ l2s,
                                            float* __restrict__ sc,
                                            int*   __restrict__ emaxb, // may be null
                                            int warp, int lane)
{
    const int idx = warp * BS + lane;
    float v = in[idx];
    float a = fabsf(v);

    float m = a;
    #pragma unroll
    for (int off = 16; off; off >>= 1)
        m = fmaxf(m, __shfl_xor_sync(0xffffffffu, m, off));

    float scale = fmaxf(m, 1e-30f);
    float xn = v / scale;
    float aq = fabsf(xn);
    float qv = 0.0f;
    if (aq > 0.0f) {
        float e = floorf(log2f(fmaxf(aq, 1e-45f)));
        float step = ldexpf(1.0f, (int)e - 3);
        if (step > 0.0f) qv = rintf(xn / step) * step;
    }
    q[idx] = qv;

    float el = (qv != 0.0f) ? floorf(log2f(fabsf(qv))) : -60.0f;
    #pragma unroll
    for (int off = 16; off; off >>= 1)
        el = fmaxf(el, __shfl_xor_sync(0xffffffffu, el, off));

    if (lane == 0) {
        l2s[warp] = log2f(scale);
        sc[warp]  = scale;
        if (emaxb) emaxb[warp] = (int)el;
    }
}

__global__ void quant_all_kernel(const float* __restrict__ x,
                                 const float* __restrict__ w)
{
    int gwarp = (blockIdx.x * blockDim.x + threadIdx.x) >> 5;
    int lane = threadIdx.x & 31;
    if (gwarp < N_ROWS * NB) {
        quant_block(x, g_xq, g_l2xs, g_xs, g_xemax, gwarp, lane);
    } else {
        int wwarp = gwarp - N_ROWS * NB;
        if (wwarp < OUT_F * NB)
            quant_block(w, g_wq, g_l2ws, g_ws, (int*)nullptr, wwarp, lane);
    }
}

// ---------------------------------------------------------------------------
// Per-element truncated-NAF term, branchless fast path.
//   nd = C + ex (NAF digit budget). Facts (proven): nd <= 14; NAF width of the
//   normalized 24-bit mantissa is 24 or 25, so drop = width - nd >= 10 > 0,
//   and nd <= 0  <=>  drop >= width  =>  all digits dropped => val = 0.
//   Products with ep < -100 (incl. p == 0 / denormals) take the exact JAX
//   slow path; statically never reached for this data (uniform branch).
// ---------------------------------------------------------------------------
__device__ __forceinline__ float naf_term(float xv, float wv, int C, float sbb,
                                          float acc)
{
    float p = xv * wv;
    int pb = __float_as_int(p);
    int pe = pb & 0x7f800000;                 // biased exponent field of p
    if (pe >= (27 << 23)) {                   // ep >= -100 (virtually always)
        int ex = ((__float_as_int(xv) >> 23) & 255) - 127;  // floor(log2|x_q|)
        int nd = C + ex;
        unsigned xs = (unsigned)(pb & 0x7FFFFF) | 0x800000u;  // exact x_scaled
        unsigned xh = xs >> 1;
        unsigned s  = xs + xh;
        unsigned npos = s & ~xh;
        unsigned nneg = xh & ~s;
        int drop = min(32 - __clz(npos | nneg) - nd, 31);    // >= 10; nd<=0 self-zeroes
        unsigned keep = 0xFFFFFFFFu << drop;
        int val = (int)(npos & keep) - (int)(nneg & keep);
        float recon = (float)val * __int_as_float(pe - (23 << 23)); // * 2^(ep-23)
        acc = fmaf(sbb, copysignf(recon, p), acc);
    } else if (pb & 0x7fffffff) {
        // exact JAX clip(23 - msb, -126, 126) semantics (p != 0, tiny/denormal)
        int ep = (pe >> 23) - 127;
        int ex = ((__float_as_int(xv) >> 23) & 255) - 127;
        int nd = C + ex;
        int shift = min(23 - ep, 126);
        unsigned xs = (unsigned)rintf(ldexpf(fabsf(p), shift));
        unsigned xh = xs >> 1;
        unsigned s  = xs + xh;
        unsigned npos = s & ~xh;
        unsigned nneg = xh & ~s;
        unsigned comb = npos | nneg;
        int width = comb ? (32 - __clz(comb)) : 0;
        int drop = min(max(width - nd, 0), 31);
        unsigned keep = 0xFFFFFFFFu << drop;
        int val = (int)(npos & keep) - (int)(nneg & keep);
        float recon = ldexpf((float)val, -shift);
        acc = fmaf(sbb, copysignf(recon, p), acc);
    }
    return acc;
}

// ---------------------------------------------------------------------------
// Main kernel: one warp per (n, o). 8 warps/CTA share the same n (x row in
// shared memory, float4). Lane handles 4 consecutive elements per iteration
// (all in one 32-elem block); 8 iterations cover 4 blocks each.
// ---------------------------------------------------------------------------
__global__ void __launch_bounds__(256, 8)
msd_gemm_kernel(const float* __restrict__ bias, float* __restrict__ out)
{
    const int warp = threadIdx.x >> 5;
    const int lane = threadIdx.x & 31;
    const int wglob = blockIdx.x * WARPS_PER_CTA + warp;
    const int n = wglob >> 9;        // /OUT_F
    const int o = wglob & (OUT_F - 1);

    __shared__ float4 s_x4[IN_F / 4];
    __shared__ float s_l2xs[NB];
    __shared__ float s_xs[NB];
    __shared__ int   s_xemax[NB];

    for (int i = threadIdx.x; i < IN_F / 4; i += 256)
        s_x4[i] = ((const float4*)(g_xq + n * IN_F))[i];
    if (threadIdx.x < NB) {
        s_l2xs[threadIdx.x]  = g_l2xs[n * NB + threadIdx.x];
        s_xs[threadIdx.x]    = g_xs[n * NB + threadIdx.x];
        s_xemax[threadIdx.x] = g_xemax[n * NB + threadIdx.x];
    }
    __syncthreads();

    // per-block (lane = block index) setup
    float l2 = s_l2xs[lane] + __ldg(&g_l2ws[o * NB + lane]);
    int ce = (int)floorf(l2);
    int emax = ce;
    #pragma unroll
    for (int off = 16; off; off >>= 1)
        emax = max(emax, __shfl_xor_sync(0xffffffffu, emax, off));

    float sb = s_xs[lane] * __ldg(&g_ws[o * NB + lane]);
    int   Cb = NDELAY - (emax - ce) - s_xemax[lane];

    const float4* wrow4 = (const float4*)(g_wq + o * IN_F);
    const int sub = lane >> 3;            // block-within-group of this lane

    float acc0 = 0.0f, acc1 = 0.0f, acc2 = 0.0f, acc3 = 0.0f;
    #pragma unroll
    for (int b = 0; b < 8; b++) {
        int blk = b * 4 + sub;
        float sbb = __shfl_sync(0xffffffffu, sb, blk);
        int   C   = __shfl_sync(0xffffffffu, Cb, blk);
        float4 xv = s_x4[b * 32 + lane];
        float4 wv = __ldg(&wrow4[b * 32 + lane]);
        acc0 = naf_term(xv.x, wv.x, C, sbb, acc0);
        acc1 = naf_term(xv.y, wv.y, C, sbb, acc1);
        acc2 = naf_term(xv.z, wv.z, C, sbb, acc2);
        acc3 = naf_term(xv.w, wv.w, C, sbb, acc3);
    }
    float acc = (acc0 + acc1) + (acc2 + acc3);

    #pragma unroll
    for (int off = 16; off; off >>= 1)
        acc += __shfl_xor_sync(0xffffffffu, acc, off);

    if (lane == 0)
        out[n * OUT_F + o] = acc + __ldg(&bias[o]);
}

extern "C" void kernel_launch(void* const* d_in, const int* in_sizes, int n_in,
                              void* d_out, int out_size)
{
    const float* x = (const float*)d_in[0];
    const float* w = (const float*)d_in[1];
    const float* bias = (const float*)d_in[2];
    float* out = (float*)d_out;
    (void)in_sizes; (void)n_in; (void)out_size;

    // Quantize x (4096 blocks) + w (16384 blocks) in one launch
    {
        int total_warps = (N_ROWS + OUT_F) * NB;
        quant_all_kernel<<<(total_warps * 32 + 255) / 256, 256>>>(x, w);
    }
    // Main: one warp per (n,o); 65536 warps, 8 warps/CTA -> 8192 CTAs
    msd_gemm_kernel<<<(N_ROWS * OUT_F) / WARPS_PER_CTA, 256>>>(bias, out);
}